// round 11
// baseline (speedup 1.0000x reference)
#include <cuda_runtime.h>
#include <cstdint>
#include <cstddef>

// GRU scan, T=1024, rows=128, H=256. 16 clusters x 8 CTAs, 512 threads/CTA.
// R7 structure (split cluster barrier per step), with matvec3 converted from
// fma.rn.f32x2 (suspected slow FP64-pipe op on sm_103a) to scalar FFMA.
// warps 0-7  (h-group): recurrent matvecs + gates for step t  (serial path)
// warps 8-15 (x-group): input projections for step t+1

#define NT   1024
#define NR   128
#define NH   256
#define CSIZE 8
#define RPC  8
#define CPC  32
#define HSTRIDE 260        // h/x row stride (k-half 1 starts at +132)
#define HBUF (RPC*HSTRIDE)
#define WMAT 8192          // floats per weight matrix slice (32 cols x 256)

#define SMEM_FLOATS (6*WMAT + 2*HBUF + HBUF + 2*3*256 + 256 + 128)
#define SMEM_BYTES  (SMEM_FLOATS*4)   // 229248 B

__device__ __forceinline__ float tanh_fast(float x) {
    float y; asm("tanh.approx.f32 %0, %1;" : "=f"(y) : "f"(x)); return y;
}
__device__ __forceinline__ float sigf(float x) { return fmaf(0.5f, tanh_fast(0.5f*x), 0.5f); }
__device__ __forceinline__ int kmap(int j) { return j + ((j >> 7) << 2); }

#define CLUSTER_ARRIVE() asm volatile("barrier.cluster.arrive.aligned;" ::: "memory")
#define CLUSTER_WAIT()   asm volatile("barrier.cluster.wait.aligned;"   ::: "memory")

extern __shared__ float smem[];

// 3-matrix x 2-row half-K matvec, scalar FFMA, even/odd accumulator pairs.
// shfl.bfly(16) K-reduce at the end.
__device__ __forceinline__ void matvec3(const float* Wbase, const float* vrows,
                                        int col, int kh, int c0, int r0, int r1,
                                        float* s /*[6]*/)
{
    const float4* W0 = (const float4*)(Wbase + 0*WMAT + (col*64 + kh*32)*4);
    const float4* W1 = (const float4*)(Wbase + 1*WMAT + (col*64 + kh*32)*4);
    const float4* W2 = (const float4*)(Wbase + 2*WMAT + (col*64 + kh*32)*4);
    const float4* V0 = (const float4*)(vrows + r0*HSTRIDE + kh*132);
    const float4* V1 = (const float4*)(vrows + r1*HSTRIDE + kh*132);
    float e0=0,o0=0,e1=0,o1=0,e2=0,o2=0,e3=0,o3=0,e4=0,o4=0,e5=0,o5=0;
    #pragma unroll 2
    for (int k4 = 0; k4 < 32; k4++) {
        int k4x = k4 ^ c0;
        float4 w0 = W0[k4x], w1 = W1[k4x], w2 = W2[k4x];
        float4 v0 = V0[k4],  v1 = V1[k4];
        e0 = fmaf(w0.x, v0.x, fmaf(w0.z, v0.z, e0));
        o0 = fmaf(w0.y, v0.y, fmaf(w0.w, v0.w, o0));
        e1 = fmaf(w1.x, v0.x, fmaf(w1.z, v0.z, e1));
        o1 = fmaf(w1.y, v0.y, fmaf(w1.w, v0.w, o1));
        e2 = fmaf(w2.x, v0.x, fmaf(w2.z, v0.z, e2));
        o2 = fmaf(w2.y, v0.y, fmaf(w2.w, v0.w, o2));
        e3 = fmaf(w0.x, v1.x, fmaf(w0.z, v1.z, e3));
        o3 = fmaf(w0.y, v1.y, fmaf(w0.w, v1.w, o3));
        e4 = fmaf(w1.x, v1.x, fmaf(w1.z, v1.z, e4));
        o4 = fmaf(w1.y, v1.y, fmaf(w1.w, v1.w, o4));
        e5 = fmaf(w2.x, v1.x, fmaf(w2.z, v1.z, e5));
        o5 = fmaf(w2.y, v1.y, fmaf(w2.w, v1.w, o5));
    }
    s[0]=e0+o0; s[1]=e1+o1; s[2]=e2+o2;
    s[3]=e3+o3; s[4]=e4+o4; s[5]=e5+o5;
    #pragma unroll
    for (int i = 0; i < 6; i++) s[i] += __shfl_xor_sync(0xffffffffu, s[i], 16);
}

__global__ void __launch_bounds__(512, 1) __cluster_dims__(CSIZE, 1, 1)
gru_scan(const float* __restrict__ ins, const int* __restrict__ resets,
         const float* __restrict__ h0,
         const float* __restrict__ Wir, const float* __restrict__ Wiz, const float* __restrict__ Win,
         const float* __restrict__ bir, const float* __restrict__ biz, const float* __restrict__ bin,
         const float* __restrict__ Whr, const float* __restrict__ Whz, const float* __restrict__ Whn,
         const float* __restrict__ bhn,
         float* __restrict__ out)
{
    float* Ws  = smem;               // [6][WMAT]  XOR-swizzled weights
    float* hb  = Ws + 6*WMAT;        // [2][HBUF]  h double buffer
    float* xs  = hb + 2*HBUF;        // [HBUF]     staged ins slice
    float* xg  = xs + HBUF;          // [2][3][256] x-projection double buffer
    float* stg = xg + 2*3*256;       // [8][32]    new-h staging
    float* bsm = stg + 256;          // [4][32]    biases

    const int tid   = threadIdx.x;
    const int rank  = blockIdx.x & (CSIZE-1);
    const int rbase = (blockIdx.x / CSIZE) * RPC;
    const int jbase = rank * CPC;

    // ---- weights: gmem [k][j] -> smem swizzled [m][col][kh][k4x][k&3]
    {
        const float* srcs[6] = {Wir, Wiz, Win, Whr, Whz, Whn};
        int jj2 = tid & 31, ks = tid >> 5;
        #pragma unroll
        for (int m = 0; m < 6; m++) {
            const float* Wm = srcs[m];
            for (int k0 = 0; k0 < NH; k0 += 16) {
                int k  = k0 + ks;
                float v = Wm[(size_t)k*NH + jbase + jj2];
                int k4 = (k >> 2) & 31, kh = k >> 7;
                int cc = ((kh << 2) ^ (jj2 & 3));
                int pos4 = jj2*64 + kh*32 + (k4 ^ cc);
                Ws[m*WMAT + pos4*4 + (k & 3)] = v;
            }
        }
    }
    if (tid < CPC) {
        bsm[tid]      = bir[jbase + tid];
        bsm[32 + tid] = biz[jbase + tid];
        bsm[64 + tid] = bin[jbase + tid];
        bsm[96 + tid] = bhn[jbase + tid];
    }
    // ---- h0 -> hb buf0 ; ins[0] -> xs
    {
        int r = tid >> 6, j = (tid & 63) * 4;
        int pos = r*HSTRIDE + kmap(j);
        *(float4*)(hb + pos) = ((const float4*)h0)[(size_t)rbase*64 + tid];
        *(float4*)(xs + pos) = ((const float4*)ins)[(size_t)rbase*64 + tid];
    }
    __syncthreads();

    // ---- lane mapping
    const bool is_h = (tid < 256);
    const int gtid = tid & 255;
    const int w    = gtid >> 5;
    const int lane = gtid & 31;
    const int colg = lane & 3, rowb = (lane >> 2) & 3, kh = lane >> 4;
    const int col  = w*4 + colg;
    const int r0   = rowb*2, r1 = r0 + 1;
    const int c0   = (kh << 2) ^ colg;
    const float c_bir = bsm[col], c_biz = bsm[32+col], c_bin = bsm[64+col], c_bhn = bsm[96+col];

    float4 px0, px1;
    int   f0 = 0, f1 = 0;
    if (!is_h) {
        float s[6];
        matvec3(Ws, xs, col, kh, c0, r0, r1, s);
        if (kh == 0) {
            float* g = xg;
            g[0*256 + r0*32 + col] = s[0] + c_bir;
            g[1*256 + r0*32 + col] = s[1] + c_biz;
            g[2*256 + r0*32 + col] = s[2] + c_bin;
            g[0*256 + r1*32 + col] = s[3] + c_bir;
            g[1*256 + r1*32 + col] = s[4] + c_biz;
            g[2*256 + r1*32 + col] = s[5] + c_bin;
        }
        px0 = ((const float4*)ins)[(size_t)(1*NR + rbase)*64 + gtid];
        px1 = ((const float4*)ins)[(size_t)(1*NR + rbase)*64 + gtid + 256];
    } else {
        f0 = resets[rbase + r0];
        f1 = resets[rbase + r1];
    }
    CLUSTER_ARRIVE();   // releases weights/h0/xg0; pairs with wait at t=0

    const uint32_t hb_s = (uint32_t)__cvta_generic_to_shared(hb);

    for (int t = 0; t < NT; t++) {
        const int p = t & 1;
        float* hcur = hb + p*HBUF;

        CLUSTER_WAIT();   // acquire peers' h pushes + xg handoff

        if (is_h) {
            float m0 = f0 ? 0.0f : 1.0f;
            float m1 = f1 ? 0.0f : 1.0f;
            {   // prefetch next step's reset flags
                int tn = (t+1 < NT) ? (t+1) : (NT-1);
                f0 = resets[(size_t)tn*NR + rbase + r0];
                f1 = resets[(size_t)tn*NR + rbase + r1];
            }

            float s[6];
            matvec3(Ws + 3*WMAT, hcur, col, kh, c0, r0, r1, s);

            float hold0 = m0 * hcur[r0*HSTRIDE + kmap(jbase + col)];
            float hold1 = m1 * hcur[r1*HSTRIDE + kmap(jbase + col)];
            const float* xgp = xg + p*768;
            float xr0 = xgp[0*256 + r0*32 + col], xz0 = xgp[1*256 + r0*32 + col], xn0 = xgp[2*256 + r0*32 + col];
            float xr1 = xgp[0*256 + r1*32 + col], xz1 = xgp[1*256 + r1*32 + col], xn1 = xgp[2*256 + r1*32 + col];

            float rr0 = sigf(xr0 + m0*s[0]);
            float zz0 = sigf(xz0 + m0*s[1]);
            float nn0 = tanh_fast(xn0 + rr0*(m0*s[2] + c_bhn));
            float hn0 = (1.0f - zz0)*nn0 + zz0*hold0;
            float rr1 = sigf(xr1 + m1*s[3]);
            float zz1 = sigf(xz1 + m1*s[4]);
            float nn1 = tanh_fast(xn1 + rr1*(m1*s[5] + c_bhn));
            float hn1 = (1.0f - zz1)*nn1 + zz1*hold1;

            if (kh == 0) {
                stg[r0*32 + col] = hn0;
                stg[r1*32 + col] = hn1;
            }
            asm volatile("bar.sync 1, 256;" ::: "memory");

            // coalesced output: 64 threads write the full 8x32 slice as float4
            if (tid < 64) {
                int r = tid >> 3, c4 = tid & 7;
                float4 v = ((const float4*)stg)[r*8 + c4];
                *(float4*)(out + ((size_t)t*NR + rbase + r)*NH + jbase + c4*4) = v;
            }
            // DSMEM broadcast to all 8 cluster CTAs' next h buffer
            if (tid < 128) {
                const uint32_t hn_off = hb_s + (uint32_t)((1-p)*HBUF)*4u;
                #pragma unroll
                for (int q = 0; q < 4; q++) {
                    int c   = tid + q*128;            // (rank, row, col-chunk)
                    int rk  = c >> 6;
                    int f4  = c & 63;
                    int row = f4 >> 3;
                    int c4  = f4 & 7;
                    float4 v = ((const float4*)stg)[row*8 + c4];
                    int jfull = jbase + c4*4;
                    uint32_t laddr = hn_off + (uint32_t)(row*HSTRIDE + kmap(jfull))*4u;
                    uint32_t raddr;
                    asm("mapa.shared::cluster.u32 %0, %1, %2;" : "=r"(raddr) : "r"(laddr), "r"(rk));
                    asm volatile("st.shared::cluster.v4.f32 [%0], {%1,%2,%3,%4};"
                                 :: "r"(raddr), "f"(v.x), "f"(v.y), "f"(v.z), "f"(v.w) : "memory");
                }
            }
        } else {
            // ---- x-group: stage ins[t+1] into xs, project for step t+1
            {
                int i0 = gtid, i1 = gtid + 256;
                int ra = i0 >> 6, ja = (i0 & 63) * 4;
                int rb = i1 >> 6, jb = (i1 & 63) * 4;
                *(float4*)(xs + ra*HSTRIDE + kmap(ja)) = px0;
                *(float4*)(xs + rb*HSTRIDE + kmap(jb)) = px1;
            }
            asm volatile("bar.sync 2, 256;" ::: "memory");

            float s[6];
            matvec3(Ws, xs, col, kh, c0, r0, r1, s);
            if (kh == 0) {
                float* g = xg + (1-p)*768;
                g[0*256 + r0*32 + col] = s[0] + c_bir;
                g[1*256 + r0*32 + col] = s[1] + c_biz;
                g[2*256 + r0*32 + col] = s[2] + c_bin;
                g[0*256 + r1*32 + col] = s[3] + c_bir;
                g[1*256 + r1*32 + col] = s[4] + c_biz;
                g[2*256 + r1*32 + col] = s[5] + c_bin;
            }
            // prefetch ins[t+2] (clamped)
            int tp = (t+2 < NT) ? (t+2) : (NT-1);
            px0 = ((const float4*)ins)[(size_t)(tp*NR + rbase)*64 + gtid];
            px1 = ((const float4*)ins)[(size_t)(tp*NR + rbase)*64 + gtid + 256];
        }

        CLUSTER_ARRIVE();   // release h pushes + xg writes; wait at top of t+1
    }
}

extern "C" void kernel_launch(void* const* d_in, const int* in_sizes, int n_in,
                              void* d_out, int out_size)
{
    const float* ins    = (const float*)d_in[0];
    const int*   resets = (const int*)d_in[1];     // jax bool -> int32 in harness
    const float* h0     = (const float*)d_in[2];
    const float* Wir    = (const float*)d_in[3];
    const float* Wiz    = (const float*)d_in[4];
    const float* Win    = (const float*)d_in[5];
    const float* bir    = (const float*)d_in[6];
    const float* biz    = (const float*)d_in[7];
    const float* bin    = (const float*)d_in[8];
    const float* Whr    = (const float*)d_in[9];
    const float* Whz    = (const float*)d_in[10];
    const float* Whn    = (const float*)d_in[11];
    const float* bhn    = (const float*)d_in[12];
    float* out = (float*)d_out;

    cudaFuncSetAttribute(gru_scan, cudaFuncAttributeMaxDynamicSharedMemorySize, SMEM_BYTES);
    gru_scan<<<NR, 512, SMEM_BYTES>>>(ins, resets, h0,
                                      Wir, Wiz, Win, bir, biz, bin,
                                      Whr, Whz, Whn, bhn, out);
}

// round 13
// speedup vs baseline: 2.0287x; 2.0287x over previous
#include <cuda_runtime.h>
#include <cstdint>
#include <cstddef>

// GRU scan, T=1024, rows=128, H=256. NO clusters. 128 independent CTAs,
// 512 threads each; groups of 8 CTAs cooperate on 8 rows via L2:
//   - new h is written to out[t] (it IS the output) with STG
//   - one red.release.gpu.add per CTA per step on a per-group counter
//   - consumers spin on ld.acquire.gpu until count >= 8*t, then LDG out[t-1]
// Exchange data is at fresh addresses every step -> no L1 staleness, and no
// cluster-scope fences -> no CCTL.IVALL L1 flush per step.
// warps 0-7  (h-group): recurrent matvec + gates for step t (serial path)
// warps 8-15 (x-group): input projections for step t+1

#define NT   1024
#define NR   128
#define NH   256
#define CSIZE 8
#define RPC  8
#define CPC  32
#define HSTRIDE 260        // h/x row stride (k-half 1 starts at +132)
#define HBUF (RPC*HSTRIDE)
#define WMAT 8192          // floats per weight matrix slice (32 cols x 256)

#define SMEM_FLOATS (6*WMAT + HBUF + HBUF + 2*3*256 + 256 + 128)
#define SMEM_BYTES  (SMEM_FLOATS*4)   // 220928 B

__device__ __align__(128) unsigned int g_flag[16*32];   // one counter per group, padded

__device__ __forceinline__ float tanh_fast(float x) {
    float y; asm("tanh.approx.f32 %0, %1;" : "=f"(y) : "f"(x)); return y;
}
__device__ __forceinline__ float sigf(float x) { return fmaf(0.5f, tanh_fast(0.5f*x), 0.5f); }
__device__ __forceinline__ int kmap(int j) { return j + ((j >> 7) << 2); }

extern __shared__ float smem[];

// 3-matrix x 2-row half-K matvec, scalar FFMA, even/odd accumulator pairs.
// shfl.bfly(16) K-reduce at the end.
__device__ __forceinline__ void matvec3(const float* Wbase, const float* vrows,
                                        int col, int kh, int c0, int r0, int r1,
                                        float* s /*[6]*/)
{
    const float4* W0 = (const float4*)(Wbase + 0*WMAT + (col*64 + kh*32)*4);
    const float4* W1 = (const float4*)(Wbase + 1*WMAT + (col*64 + kh*32)*4);
    const float4* W2 = (const float4*)(Wbase + 2*WMAT + (col*64 + kh*32)*4);
    const float4* V0 = (const float4*)(vrows + r0*HSTRIDE + kh*132);
    const float4* V1 = (const float4*)(vrows + r1*HSTRIDE + kh*132);
    float e0=0,o0=0,e1=0,o1=0,e2=0,o2=0,e3=0,o3=0,e4=0,o4=0,e5=0,o5=0;
    #pragma unroll 2
    for (int k4 = 0; k4 < 32; k4++) {
        int k4x = k4 ^ c0;
        float4 w0 = W0[k4x], w1 = W1[k4x], w2 = W2[k4x];
        float4 v0 = V0[k4],  v1 = V1[k4];
        e0 = fmaf(w0.x, v0.x, fmaf(w0.z, v0.z, e0));
        o0 = fmaf(w0.y, v0.y, fmaf(w0.w, v0.w, o0));
        e1 = fmaf(w1.x, v0.x, fmaf(w1.z, v0.z, e1));
        o1 = fmaf(w1.y, v0.y, fmaf(w1.w, v0.w, o1));
        e2 = fmaf(w2.x, v0.x, fmaf(w2.z, v0.z, e2));
        o2 = fmaf(w2.y, v0.y, fmaf(w2.w, v0.w, o2));
        e3 = fmaf(w0.x, v1.x, fmaf(w0.z, v1.z, e3));
        o3 = fmaf(w0.y, v1.y, fmaf(w0.w, v1.w, o3));
        e4 = fmaf(w1.x, v1.x, fmaf(w1.z, v1.z, e4));
        o4 = fmaf(w1.y, v1.y, fmaf(w1.w, v1.w, o4));
        e5 = fmaf(w2.x, v1.x, fmaf(w2.z, v1.z, e5));
        o5 = fmaf(w2.y, v1.y, fmaf(w2.w, v1.w, o5));
    }
    s[0]=e0+o0; s[1]=e1+o1; s[2]=e2+o2;
    s[3]=e3+o3; s[4]=e4+o4; s[5]=e5+o5;
    #pragma unroll
    for (int i = 0; i < 6; i++) s[i] += __shfl_xor_sync(0xffffffffu, s[i], 16);
}

__global__ void __launch_bounds__(512, 1)
gru_scan(const float* __restrict__ ins, const int* __restrict__ resets,
         const float* __restrict__ h0,
         const float* __restrict__ Wir, const float* __restrict__ Wiz, const float* __restrict__ Win,
         const float* __restrict__ bir, const float* __restrict__ biz, const float* __restrict__ bin,
         const float* __restrict__ Whr, const float* __restrict__ Whz, const float* __restrict__ Whn,
         const float* __restrict__ bhn,
         float* __restrict__ out)
{
    float* Ws  = smem;               // [6][WMAT]  XOR-swizzled weights
    float* hb  = Ws + 6*WMAT;        // [HBUF]     h buffer (single)
    float* xs  = hb + HBUF;          // [HBUF]     staged ins slice
    float* xg  = xs + HBUF;          // [2][3][256] x-projection double buffer
    float* stg = xg + 2*3*256;       // [8][32]    new-h staging
    float* bsm = stg + 256;          // [4][32]    biases

    const int tid   = threadIdx.x;
    const int rank  = blockIdx.x & (CSIZE-1);
    const int grp   = blockIdx.x >> 3;           // 16 groups of 8 CTAs
    const int rbase = grp * RPC;
    const int jbase = rank * CPC;
    unsigned int* gf = &g_flag[grp*32];

    // ---- weights: gmem [k][j] -> smem swizzled [m][col][kh][k4x][k&3]
    {
        const float* srcs[6] = {Wir, Wiz, Win, Whr, Whz, Whn};
        int jj2 = tid & 31, ks = tid >> 5;
        #pragma unroll
        for (int m = 0; m < 6; m++) {
            const float* Wm = srcs[m];
            for (int k0 = 0; k0 < NH; k0 += 16) {
                int k  = k0 + ks;
                float v = Wm[(size_t)k*NH + jbase + jj2];
                int k4 = (k >> 2) & 31, kh = k >> 7;
                int cc = ((kh << 2) ^ (jj2 & 3));
                int pos4 = jj2*64 + kh*32 + (k4 ^ cc);
                Ws[m*WMAT + pos4*4 + (k & 3)] = v;
            }
        }
    }
    if (tid < CPC) {
        bsm[tid]      = bir[jbase + tid];
        bsm[32 + tid] = biz[jbase + tid];
        bsm[64 + tid] = bin[jbase + tid];
        bsm[96 + tid] = bhn[jbase + tid];
    }
    // ---- h0 -> hb ; ins[0] -> xs
    {
        int r = tid >> 6, j = (tid & 63) * 4;
        int pos = r*HSTRIDE + kmap(j);
        *(float4*)(hb + pos) = ((const float4*)h0)[(size_t)rbase*64 + tid];
        *(float4*)(xs + pos) = ((const float4*)ins)[(size_t)rbase*64 + tid];
    }
    __syncthreads();

    // ---- lane mapping
    const bool is_h = (tid < 256);
    const int gtid = tid & 255;
    const int w    = gtid >> 5;
    const int lane = gtid & 31;
    const int colg = lane & 3, rowb = (lane >> 2) & 3, kh = lane >> 4;
    const int col  = w*4 + colg;
    const int r0   = rowb*2, r1 = r0 + 1;
    const int c0   = (kh << 2) ^ colg;
    const float c_bir = bsm[col], c_biz = bsm[32+col], c_bin = bsm[64+col], c_bhn = bsm[96+col];

    float4 px0, px1;
    int   f0 = 0, f1 = 0;
    if (!is_h) {
        float s[6];
        matvec3(Ws, xs, col, kh, c0, r0, r1, s);
        if (kh == 0) {
            float* g = xg;
            g[0*256 + r0*32 + col] = s[0] + c_bir;
            g[1*256 + r0*32 + col] = s[1] + c_biz;
            g[2*256 + r0*32 + col] = s[2] + c_bin;
            g[0*256 + r1*32 + col] = s[3] + c_bir;
            g[1*256 + r1*32 + col] = s[4] + c_biz;
            g[2*256 + r1*32 + col] = s[5] + c_bin;
        }
        px0 = ((const float4*)ins)[(size_t)(1*NR + rbase)*64 + gtid];
        px1 = ((const float4*)ins)[(size_t)(1*NR + rbase)*64 + gtid + 256];
    } else {
        f0 = resets[rbase + r0];
        f1 = resets[rbase + r1];
    }
    __syncthreads();   // xg[0] + weights visible CTA-wide

    for (int t = 0; t < NT; t++) {
        const int p = t & 1;

        if (is_h) {
            if (t > 0) {
                // wait for all 8 CTAs' step-(t-1) pushes, then pull out[t-1]
                const unsigned int target = 8u * (unsigned int)t;
                unsigned int v;
                do {
                    asm volatile("ld.acquire.gpu.global.u32 %0, [%1];"
                                 : "=r"(v) : "l"(gf) : "memory");
                } while (v < target);
                #pragma unroll
                for (int q = 0; q < 2; q++) {
                    int f = gtid + q*256;
                    int r = f >> 6, c4 = f & 63;
                    float4 hv = *(const float4*)(out + ((size_t)(t-1)*NR + rbase + r)*NH + c4*4);
                    *(float4*)(hb + r*HSTRIDE + kmap(c4*4)) = hv;
                }
                asm volatile("bar.sync 1, 256;" ::: "memory");
            }

            float m0 = f0 ? 0.0f : 1.0f;
            float m1 = f1 ? 0.0f : 1.0f;
            {   // prefetch next step's reset flags
                int tn = (t+1 < NT) ? (t+1) : (NT-1);
                f0 = resets[(size_t)tn*NR + rbase + r0];
                f1 = resets[(size_t)tn*NR + rbase + r1];
            }

            float s[6];
            matvec3(Ws + 3*WMAT, hb, col, kh, c0, r0, r1, s);

            float hold0 = m0 * hb[r0*HSTRIDE + kmap(jbase + col)];
            float hold1 = m1 * hb[r1*HSTRIDE + kmap(jbase + col)];
            const float* xgp = xg + p*768;
            float xr0 = xgp[0*256 + r0*32 + col], xz0 = xgp[1*256 + r0*32 + col], xn0 = xgp[2*256 + r0*32 + col];
            float xr1 = xgp[0*256 + r1*32 + col], xz1 = xgp[1*256 + r1*32 + col], xn1 = xgp[2*256 + r1*32 + col];

            float rr0 = sigf(xr0 + m0*s[0]);
            float zz0 = sigf(xz0 + m0*s[1]);
            float nn0 = tanh_fast(xn0 + rr0*(m0*s[2] + c_bhn));
            float hn0 = (1.0f - zz0)*nn0 + zz0*hold0;
            float rr1 = sigf(xr1 + m1*s[3]);
            float zz1 = sigf(xz1 + m1*s[4]);
            float nn1 = tanh_fast(xn1 + rr1*(m1*s[5] + c_bhn));
            float hn1 = (1.0f - zz1)*nn1 + zz1*hold1;

            if (kh == 0) {
                stg[r0*32 + col] = hn0;
                stg[r1*32 + col] = hn1;
            }
            asm volatile("bar.sync 1, 256;" ::: "memory");

            // write out[t] (this IS the h exchange buffer), coalesced
            if (tid < 64) {
                int r = tid >> 3, c4 = tid & 7;
                float4 v = ((const float4*)stg)[r*8 + c4];
                *(float4*)(out + ((size_t)t*NR + rbase + r)*NH + jbase + c4*4) = v;
            }
            asm volatile("bar.sync 1, 256;" ::: "memory");   // STGs ordered before release
            if (tid == 0) {
                asm volatile("red.release.gpu.global.add.u32 [%0], %1;"
                             :: "l"(gf), "r"(1u) : "memory");
            }
        } else {
            // ---- x-group: stage ins[t+1] into xs, project for step t+1
            {
                int i0 = gtid, i1 = gtid + 256;
                int ra = i0 >> 6, ja = (i0 & 63) * 4;
                int rb = i1 >> 6, jb = (i1 & 63) * 4;
                *(float4*)(xs + ra*HSTRIDE + kmap(ja)) = px0;
                *(float4*)(xs + rb*HSTRIDE + kmap(jb)) = px1;
            }
            asm volatile("bar.sync 2, 256;" ::: "memory");

            float s[6];
            matvec3(Ws, xs, col, kh, c0, r0, r1, s);
            if (kh == 0) {
                float* g = xg + (1-p)*768;
                g[0*256 + r0*32 + col] = s[0] + c_bir;
                g[1*256 + r0*32 + col] = s[1] + c_biz;
                g[2*256 + r0*32 + col] = s[2] + c_bin;
                g[0*256 + r1*32 + col] = s[3] + c_bir;
                g[1*256 + r1*32 + col] = s[4] + c_biz;
                g[2*256 + r1*32 + col] = s[5] + c_bin;
            }
            int tp = (t+2 < NT) ? (t+2) : (NT-1);
            px0 = ((const float4*)ins)[(size_t)(tp*NR + rbase)*64 + gtid];
            px1 = ((const float4*)ins)[(size_t)(tp*NR + rbase)*64 + gtid + 256];
        }

        __syncthreads();   // intra-CTA x<->h handoff (xg / xs buffers)
    }

    // reset the group counter for the next graph replay (rank 0 only, after
    // confirming all 8 CTAs' final arrivals landed)
    if (rank == 0 && tid == 0) {
        const unsigned int target = 8u * (unsigned int)NT;
        unsigned int v;
        do {
            asm volatile("ld.acquire.gpu.global.u32 %0, [%1];"
                         : "=r"(v) : "l"(gf) : "memory");
        } while (v < target);
        asm volatile("st.relaxed.gpu.global.u32 [%0], %1;" :: "l"(gf), "r"(0u) : "memory");
    }
}

extern "C" void kernel_launch(void* const* d_in, const int* in_sizes, int n_in,
                              void* d_out, int out_size)
{
    const float* ins    = (const float*)d_in[0];
    const int*   resets = (const int*)d_in[1];     // jax bool -> int32 in harness
    const float* h0     = (const float*)d_in[2];
    const float* Wir    = (const float*)d_in[3];
    const float* Wiz    = (const float*)d_in[4];
    const float* Win    = (const float*)d_in[5];
    const float* bir    = (const float*)d_in[6];
    const float* biz    = (const float*)d_in[7];
    const float* bin    = (const float*)d_in[8];
    const float* Whr    = (const float*)d_in[9];
    const float* Whz    = (const float*)d_in[10];
    const float* Whn    = (const float*)d_in[11];
    const float* bhn    = (const float*)d_in[12];
    float* out = (float*)d_out;

    cudaFuncSetAttribute(gru_scan, cudaFuncAttributeMaxDynamicSharedMemorySize, SMEM_BYTES);
    gru_scan<<<NR, 512, SMEM_BYTES>>>(ins, resets, h0,
                                      Wir, Wiz, Win, bir, biz, bin,
                                      Whr, Whz, Whn, bhn, out);
}